// round 9
// baseline (speedup 1.0000x reference)
#include <cuda_runtime.h>

#define BB   8
#define NN   4096
#define CC   6
#define KNBR 16
#define H1   64
#define H2   128

static __device__ int   g_nbr[BB * NN * KNBR];          // 2 MB
static __device__ float g_x1 [BB * NN * H1];            // 8 MB

#define FULLM 0xFFFFFFFFu

// ---------------------------------------------------------------------------
// Kernel 1 (fused knn + layer1): warp = 2 queries; top-17 lane-distributed
// (lanes 0..16 sorted ascending; lane 0 = self since d2(self) rounds to ~0).
// Warm start: bitonic sort of block-0 candidates. Inserts: stable warp
// insertion, tau updated once per eventful block (filter, not correctness).
// d2 bit-matches reference: d2 = fma(dot,-2, sq_i+sq_j), ascending fma dot.
// Epilogue: lanes 0..16 hold {self U nbr} -> butterfly-sum feats rows,
// 6->64 matmul + relu -> g_x1  (layer1 kernel eliminated).
// ---------------------------------------------------------------------------
__global__ __launch_bounds__(512, 3)
void knn_kernel(const float* __restrict__ feats,
                const float* __restrict__ W1,
                const float* __restrict__ b1) {
    extern __shared__ float smem_f[];
    float4* sp = (float4*)smem_f;                       // [NN] : x,y,z,sq
    float* W1s = smem_f + NN * 4;                       // CC*H1
    float* b1s = W1s + CC * H1;                         // H1

    const int b = blockIdx.y;
    const float* fb = feats + (size_t)b * NN * CC;
    for (int j = threadIdx.x; j < NN; j += blockDim.x) {
        float x = fb[j * CC + 0];
        float y = fb[j * CC + 1];
        float z = fb[j * CC + 2];
        float sq = __fadd_rn(__fadd_rn(__fmul_rn(x, x), __fmul_rn(y, y)),
                             __fmul_rn(z, z));
        sp[j] = make_float4(x, y, z, sq);
    }
    for (int t = threadIdx.x; t < CC * H1; t += blockDim.x) W1s[t] = W1[t];
    if (threadIdx.x < H1) b1s[threadIdx.x] = b1[threadIdx.x];
    __syncthreads();

    const int lane = threadIdx.x & 31;
    const int wid  = threadIdx.x >> 5;                  // 16 warps
    const int i0   = blockIdx.x * 32 + wid * 2;
    const int i1   = i0 + 1;
    const float4 qa = sp[i0];
    const float4 qb = sp[i1];

    // ---- warm start: bitonic sort of block-0's 32 candidates per query ----
    float bda, bdb;
    int   bia, bib;
    {
        float4 p = sp[lane];
        float dota = __fmaf_rn(qa.z, p.z, __fmaf_rn(qa.y, p.y, __fmul_rn(qa.x, p.x)));
        bda = __fmaf_rn(dota, -2.0f, __fadd_rn(qa.w, p.w));
        float dotb = __fmaf_rn(qb.z, p.z, __fmaf_rn(qb.y, p.y, __fmul_rn(qb.x, p.x)));
        bdb = __fmaf_rn(dotb, -2.0f, __fadd_rn(qb.w, p.w));
        bia = lane; bib = lane;

#pragma unroll
        for (int k = 2; k <= 32; k <<= 1) {
#pragma unroll
            for (int j = k >> 1; j > 0; j >>= 1) {
                bool takeSmall = ((lane & k) == 0) == ((lane & j) == 0);
                {
                    float od = __shfl_xor_sync(FULLM, bda, j);
                    int   oi = __shfl_xor_sync(FULLM, bia, j);
                    bool oLess = (od < bda) || (od == bda && oi < bia);
                    if (takeSmall == oLess) { bda = od; bia = oi; }
                }
                {
                    float od = __shfl_xor_sync(FULLM, bdb, j);
                    int   oi = __shfl_xor_sync(FULLM, bib, j);
                    bool oLess = (od < bdb) || (od == bdb && oi < bib);
                    if (takeSmall == oLess) { bdb = od; bib = oi; }
                }
            }
        }
    }
    float taua = __shfl_sync(FULLM, bda, 16);
    float taub = __shfl_sync(FULLM, bdb, 16);

    // ---- main scan ----
#pragma unroll 2
    for (int jb = 32; jb < NN; jb += 32) {
        const float4 p = sp[jb + lane];
        float dota = __fmaf_rn(qa.z, p.z, __fmaf_rn(qa.y, p.y, __fmul_rn(qa.x, p.x)));
        float d2a  = __fmaf_rn(dota, -2.0f, __fadd_rn(qa.w, p.w));
        float dotb = __fmaf_rn(qb.z, p.z, __fmaf_rn(qb.y, p.y, __fmul_rn(qb.x, p.x)));
        float d2b  = __fmaf_rn(dotb, -2.0f, __fadd_rn(qb.w, p.w));

        unsigned balA = __ballot_sync(FULLM, d2a < taua);
        unsigned balB = __ballot_sync(FULLM, d2b < taub);

        if (balA) {                                     // warp-uniform
            do {
                int src = __ffs(balA) - 1;
                balA &= balA - 1;
                float nd = __shfl_sync(FULLM, d2a, src);
                int   ni = jb + src;
                unsigned m = __ballot_sync(FULLM, nd < bda);
                float ud = __shfl_up_sync(FULLM, bda, 1);
                int   ui = __shfl_up_sync(FULLM, bia, 1);
                if (m) {
                    int pos = __ffs(m) - 1;
                    if (lane >= pos) { bda = (lane == pos) ? nd : ud;
                                       bia = (lane == pos) ? ni : ui; }
                }
            } while (balA);
            taua = __shfl_sync(FULLM, bda, 16);
        }

        if (balB) {
            do {
                int src = __ffs(balB) - 1;
                balB &= balB - 1;
                float nd = __shfl_sync(FULLM, d2b, src);
                int   ni = jb + src;
                unsigned m = __ballot_sync(FULLM, nd < bdb);
                float ud = __shfl_up_sync(FULLM, bdb, 1);
                int   ui = __shfl_up_sync(FULLM, bib, 1);
                if (m) {
                    int pos = __ffs(m) - 1;
                    if (lane >= pos) { bdb = (lane == pos) ? nd : ud;
                                       bib = (lane == pos) ? ni : ui; }
                }
            } while (balB);
            taub = __shfl_sync(FULLM, bdb, 16);
        }
    }

    if (lane >= 1 && lane < 17) {                       // lane 0 == self
        g_nbr[(b * NN + i0) * KNBR + lane - 1] = bia;
        g_nbr[(b * NN + i1) * KNBR + lane - 1] = bib;
    }

    // ---- fused layer1 epilogue: lanes 0..16 = {self U nbr(i)} ----
    float fa[CC], fc[CC];
#pragma unroll
    for (int c = 0; c < CC; ++c) { fa[c] = 0.0f; fc[c] = 0.0f; }
    if (lane < 17) {
        const float* ra = fb + (size_t)bia * CC;
        const float* rb2 = fb + (size_t)bib * CC;
#pragma unroll
        for (int c = 0; c < CC; ++c) { fa[c] = ra[c]; fc[c] = rb2[c]; }
    }
#pragma unroll
    for (int off = 16; off; off >>= 1) {
#pragma unroll
        for (int c = 0; c < CC; ++c) {
            fa[c] += __shfl_xor_sync(FULLM, fa[c], off);
            fc[c] += __shfl_xor_sync(FULLM, fc[c], off);
        }
    }

    const float inv = 1.0f / 17.0f;
    float* xoA = g_x1 + (size_t)(b * NN + i0) * H1;
    float* xoB = g_x1 + (size_t)(b * NN + i1) * H1;
#pragma unroll
    for (int u = 0; u < 2; ++u) {
        int c = lane + u * 32;
        float aA = fa[0] * W1s[c];
        float aB = fc[0] * W1s[c];
#pragma unroll
        for (int kk = 1; kk < CC; ++kk) {
            aA = fmaf(fa[kk], W1s[kk * H1 + c], aA);
            aB = fmaf(fc[kk], W1s[kk * H1 + c], aB);
        }
        xoA[c] = fmaxf(fmaf(aA, inv, b1s[c]), 0.0f);
        xoB[c] = fmaxf(fmaf(aB, inv, b1s[c]), 0.0f);
    }
}

// ---------------------------------------------------------------------------
// Kernel 3 (fused): gather-sum x1 -> x2 = relu(.@W2*inv+b2) -> out = x2@Wf+bf
// ---------------------------------------------------------------------------
__device__ __forceinline__ float f4get(float4 v, int kk) {
    return kk == 0 ? v.x : kk == 1 ? v.y : kk == 2 ? v.z : v.w;
}

#define PTS 64

__global__ __launch_bounds__(512, 1)
void layer2_kernel(const float* __restrict__ W2,
                   const float* __restrict__ b2,
                   const float* __restrict__ Wf,
                   const float* __restrict__ bf,
                   float* __restrict__ out) {
    extern __shared__ float smem_f[];
    float* W2s = smem_f;                 // 64*128
    float* Wfs = W2s + H1 * H2;          // 128*128
    float* b2s = Wfs + H2 * H2;          // 128
    float* bfs = b2s + H2;               // 128
    float* s1  = bfs + H2;               // PTS*64
    float* x2s = s1 + PTS * H1;          // PTS*128

    for (int t = threadIdx.x; t < H1 * H2; t += blockDim.x) W2s[t] = W2[t];
    for (int t = threadIdx.x; t < H2 * H2; t += blockDim.x) Wfs[t] = Wf[t];
    if (threadIdx.x < H2) { b2s[threadIdx.x] = b2[threadIdx.x]; bfs[threadIdx.x] = bf[threadIdx.x]; }

    const int lane = threadIdx.x & 31;
    const int warp = threadIdx.x >> 5;              // 16 warps
    const int gp0  = blockIdx.x * PTS;
    const int b    = gp0 >> 12;
    const float* x1b = g_x1 + (size_t)b * NN * H1;

#pragma unroll
    for (int pp = 0; pp < 4; ++pp) {
        int p  = warp * 4 + pp;
        int gi = gp0 + p;
        int li = gi & (NN - 1);
        const int* nb = g_nbr + (size_t)gi * KNBR;
        float2 v = ((const float2*)(x1b + (size_t)li * H1))[lane];
        float a0 = v.x, a1 = v.y;
#pragma unroll
        for (int n = 0; n < KNBR; ++n) {
            int j = nb[n];
            float2 w = ((const float2*)(x1b + (size_t)j * H1))[lane];
            a0 += w.x; a1 += w.y;
        }
        ((float2*)(s1 + p * H1))[lane] = make_float2(a0, a1);
    }
    __syncthreads();

    const float inv = 1.0f / 17.0f;

    {
        float acc[4][4];
#pragma unroll
        for (int pp = 0; pp < 4; ++pp)
#pragma unroll
            for (int cc = 0; cc < 4; ++cc) acc[pp][cc] = 0.0f;

#pragma unroll 4
        for (int k = 0; k < H1; k += 4) {
            float4 xv[4];
#pragma unroll
            for (int pp = 0; pp < 4; ++pp)
                xv[pp] = *(const float4*)&s1[(warp * 4 + pp) * H1 + k];
#pragma unroll
            for (int kk = 0; kk < 4; ++kk) {
                float4 w = *(const float4*)&W2s[(k + kk) * H2 + lane * 4];
#pragma unroll
                for (int pp = 0; pp < 4; ++pp) {
                    float xs = f4get(xv[pp], kk);
                    acc[pp][0] = fmaf(xs, w.x, acc[pp][0]);
                    acc[pp][1] = fmaf(xs, w.y, acc[pp][1]);
                    acc[pp][2] = fmaf(xs, w.z, acc[pp][2]);
                    acc[pp][3] = fmaf(xs, w.w, acc[pp][3]);
                }
            }
        }
#pragma unroll
        for (int pp = 0; pp < 4; ++pp) {
            float4 r;
            r.x = fmaxf(fmaf(acc[pp][0], inv, b2s[lane * 4 + 0]), 0.0f);
            r.y = fmaxf(fmaf(acc[pp][1], inv, b2s[lane * 4 + 1]), 0.0f);
            r.z = fmaxf(fmaf(acc[pp][2], inv, b2s[lane * 4 + 2]), 0.0f);
            r.w = fmaxf(fmaf(acc[pp][3], inv, b2s[lane * 4 + 3]), 0.0f);
            *(float4*)&x2s[(warp * 4 + pp) * H2 + lane * 4] = r;
        }
    }
    __syncthreads();

    {
        float acc[4][4];
#pragma unroll
        for (int pp = 0; pp < 4; ++pp)
#pragma unroll
            for (int cc = 0; cc < 4; ++cc) acc[pp][cc] = 0.0f;

#pragma unroll 4
        for (int k = 0; k < H2; k += 4) {
            float4 xv[4];
#pragma unroll
            for (int pp = 0; pp < 4; ++pp)
                xv[pp] = *(const float4*)&x2s[(warp * 4 + pp) * H2 + k];
#pragma unroll
            for (int kk = 0; kk < 4; ++kk) {
                float4 w = *(const float4*)&Wfs[(k + kk) * H2 + lane * 4];
#pragma unroll
                for (int pp = 0; pp < 4; ++pp) {
                    float xs = f4get(xv[pp], kk);
                    acc[pp][0] = fmaf(xs, w.x, acc[pp][0]);
                    acc[pp][1] = fmaf(xs, w.y, acc[pp][1]);
                    acc[pp][2] = fmaf(xs, w.z, acc[pp][2]);
                    acc[pp][3] = fmaf(xs, w.w, acc[pp][3]);
                }
            }
        }
#pragma unroll
        for (int pp = 0; pp < 4; ++pp) {
            int gi = gp0 + warp * 4 + pp;
            float4 r;
            r.x = acc[pp][0] + bfs[lane * 4 + 0];
            r.y = acc[pp][1] + bfs[lane * 4 + 1];
            r.z = acc[pp][2] + bfs[lane * 4 + 2];
            r.w = acc[pp][3] + bfs[lane * 4 + 3];
            *(float4*)&out[(size_t)gi * H2 + lane * 4] = r;
        }
    }
}

// ---------------------------------------------------------------------------
extern "C" void kernel_launch(void* const* d_in, const int* in_sizes, int n_in,
                              void* d_out, int out_size) {
    const float* feats = (const float*)d_in[0];
    const float* W1    = (const float*)d_in[1];
    const float* b1    = (const float*)d_in[2];
    const float* W2    = (const float*)d_in[3];
    const float* b2    = (const float*)d_in[4];
    const float* Wf    = (const float*)d_in[5];
    const float* bf    = (const float*)d_in[6];
    float* out = (float*)d_out;

    const int smem_knn = NN * (int)sizeof(float4)
                       + (CC * H1 + H1) * (int)sizeof(float);            // ~66 KB
    const int smem_l2  = (H1 * H2 + H2 * H2 + 2 * H2 + PTS * H1 + PTS * H2)
                         * (int)sizeof(float);                           // ~145 KB

    cudaFuncSetAttribute(knn_kernel,    cudaFuncAttributeMaxDynamicSharedMemorySize, smem_knn);
    cudaFuncSetAttribute(layer2_kernel, cudaFuncAttributeMaxDynamicSharedMemorySize, smem_l2);

    dim3 gKNN(NN / 32, BB);                       // 2 queries/warp, 16 warps/block
    knn_kernel   <<<gKNN, 512, smem_knn>>>(feats, W1, b1);
    layer2_kernel<<<(BB * NN) / PTS, 512, smem_l2>>>(W2, b2, Wf, bf, out);
}

// round 10
// speedup vs baseline: 1.6063x; 1.6063x over previous
#include <cuda_runtime.h>

#define BB   8
#define NN   4096
#define CC   6
#define KNBR 16
#define H1   64
#define H2   128

static __device__ int   g_nbr[BB * NN * KNBR];          // 2 MB
static __device__ float g_x1 [BB * NN * H1];            // 8 MB

#define FULLM 0xFFFFFFFFu

// ---------------------------------------------------------------------------
// Kernel 1: exact KNN (k=16). Warp = 2 queries; top-17 lane-distributed
// (lanes 0..16 sorted ascending; lane 0 = self because d2(self) rounds to ~0,
// below any real neighbor distance). Warm start: bitonic sort of block-0
// candidates. Inserts: per-query loops, stable warp insertion; tau updated
// once per eventful block (filter only, not a correctness input).
// d2 bit-matches reference: d2 = fma(dot,-2, sq_i+sq_j), ascending fma dot.
// ---------------------------------------------------------------------------
__global__ __launch_bounds__(512)
void knn_kernel(const float* __restrict__ feats) {
    extern __shared__ float smem_f[];
    float4* sp = (float4*)smem_f;                       // [NN] : x,y,z,sq

    const int b = blockIdx.y;
    const float* fb = feats + (size_t)b * NN * CC;
    for (int j = threadIdx.x; j < NN; j += blockDim.x) {
        float x = fb[j * CC + 0];
        float y = fb[j * CC + 1];
        float z = fb[j * CC + 2];
        float sq = __fadd_rn(__fadd_rn(__fmul_rn(x, x), __fmul_rn(y, y)),
                             __fmul_rn(z, z));
        sp[j] = make_float4(x, y, z, sq);
    }
    __syncthreads();

    const int lane = threadIdx.x & 31;
    const int wid  = threadIdx.x >> 5;                  // 16 warps
    const int i0   = blockIdx.x * 32 + wid * 2;
    const int i1   = i0 + 1;
    const float4 qa = sp[i0];
    const float4 qb = sp[i1];

    // ---- warm start: bitonic sort of block-0's 32 candidates per query ----
    float bda, bdb;
    int   bia, bib;
    {
        float4 p = sp[lane];
        float dota = __fmaf_rn(qa.z, p.z, __fmaf_rn(qa.y, p.y, __fmul_rn(qa.x, p.x)));
        bda = __fmaf_rn(dota, -2.0f, __fadd_rn(qa.w, p.w));
        float dotb = __fmaf_rn(qb.z, p.z, __fmaf_rn(qb.y, p.y, __fmul_rn(qb.x, p.x)));
        bdb = __fmaf_rn(dotb, -2.0f, __fadd_rn(qb.w, p.w));
        bia = lane; bib = lane;

#pragma unroll
        for (int k = 2; k <= 32; k <<= 1) {
#pragma unroll
            for (int j = k >> 1; j > 0; j >>= 1) {
                bool takeSmall = ((lane & k) == 0) == ((lane & j) == 0);
                {
                    float od = __shfl_xor_sync(FULLM, bda, j);
                    int   oi = __shfl_xor_sync(FULLM, bia, j);
                    bool oLess = (od < bda) || (od == bda && oi < bia);
                    if (takeSmall == oLess) { bda = od; bia = oi; }
                }
                {
                    float od = __shfl_xor_sync(FULLM, bdb, j);
                    int   oi = __shfl_xor_sync(FULLM, bib, j);
                    bool oLess = (od < bdb) || (od == bdb && oi < bib);
                    if (takeSmall == oLess) { bdb = od; bib = oi; }
                }
            }
        }
    }
    float taua = __shfl_sync(FULLM, bda, 16);
    float taub = __shfl_sync(FULLM, bdb, 16);

    // ---- main scan ----
#pragma unroll 2
    for (int jb = 32; jb < NN; jb += 32) {
        const float4 p = sp[jb + lane];
        float dota = __fmaf_rn(qa.z, p.z, __fmaf_rn(qa.y, p.y, __fmul_rn(qa.x, p.x)));
        float d2a  = __fmaf_rn(dota, -2.0f, __fadd_rn(qa.w, p.w));
        float dotb = __fmaf_rn(qb.z, p.z, __fmaf_rn(qb.y, p.y, __fmul_rn(qb.x, p.x)));
        float d2b  = __fmaf_rn(dotb, -2.0f, __fadd_rn(qb.w, p.w));

        unsigned balA = __ballot_sync(FULLM, d2a < taua);
        unsigned balB = __ballot_sync(FULLM, d2b < taub);

        if (balA) {                                     // warp-uniform
            do {
                int src = __ffs(balA) - 1;
                balA &= balA - 1;
                float nd = __shfl_sync(FULLM, d2a, src);
                int   ni = jb + src;
                unsigned m = __ballot_sync(FULLM, nd < bda);
                float ud = __shfl_up_sync(FULLM, bda, 1);
                int   ui = __shfl_up_sync(FULLM, bia, 1);
                if (m) {
                    int pos = __ffs(m) - 1;
                    if (lane >= pos) { bda = (lane == pos) ? nd : ud;
                                       bia = (lane == pos) ? ni : ui; }
                }
            } while (balA);
            taua = __shfl_sync(FULLM, bda, 16);
        }

        if (balB) {
            do {
                int src = __ffs(balB) - 1;
                balB &= balB - 1;
                float nd = __shfl_sync(FULLM, d2b, src);
                int   ni = jb + src;
                unsigned m = __ballot_sync(FULLM, nd < bdb);
                float ud = __shfl_up_sync(FULLM, bdb, 1);
                int   ui = __shfl_up_sync(FULLM, bib, 1);
                if (m) {
                    int pos = __ffs(m) - 1;
                    if (lane >= pos) { bdb = (lane == pos) ? nd : ud;
                                       bib = (lane == pos) ? ni : ui; }
                }
            } while (balB);
            taub = __shfl_sync(FULLM, bdb, 16);
        }
    }

    if (lane >= 1 && lane < 17) {                       // lane 0 == self
        g_nbr[(b * NN + i0) * KNBR + lane - 1] = bia;
        g_nbr[(b * NN + i1) * KNBR + lane - 1] = bib;
    }
}

// ---------------------------------------------------------------------------
// Kernel 2: x1 = relu( ((sum_{j in nbr(i)} feats[j]) + feats[i]) @ W1 * inv + b1 )
// ---------------------------------------------------------------------------
__global__ void layer1_kernel(const float* __restrict__ feats,
                              const float* __restrict__ W1,
                              const float* __restrict__ b1) {
    extern __shared__ float smem_f[];
    float* fs  = smem_f;                // NN*CC
    float* W1s = fs + NN * CC;          // CC*H1
    float* b1s = W1s + CC * H1;         // H1

    const int b = blockIdx.y;
    const float* fb = feats + (size_t)b * NN * CC;
    for (int t = threadIdx.x; t < NN * CC; t += blockDim.x) fs[t] = fb[t];
    for (int t = threadIdx.x; t < CC * H1; t += blockDim.x) W1s[t] = W1[t];
    if (threadIdx.x < H1) b1s[threadIdx.x] = b1[threadIdx.x];
    __syncthreads();

    const int i = blockIdx.x * blockDim.x + threadIdx.x;

    float s[CC];
#pragma unroll
    for (int c = 0; c < CC; ++c) s[c] = fs[i * CC + c];

    const int* nb = g_nbr + (size_t)(b * NN + i) * KNBR;
#pragma unroll
    for (int n = 0; n < KNBR; ++n) {
        int j = nb[n];
#pragma unroll
        for (int c = 0; c < CC; ++c) s[c] += fs[j * CC + c];
    }

    float* xo = g_x1 + (size_t)(b * NN + i) * H1;
    const float inv = 1.0f / 17.0f;
#pragma unroll 2
    for (int c4 = 0; c4 < H1; c4 += 4) {
        float r[4];
#pragma unroll
        for (int u = 0; u < 4; ++u) {
            int c = c4 + u;
            float a = s[0] * W1s[c];
#pragma unroll
            for (int kk = 1; kk < CC; ++kk) a = fmaf(s[kk], W1s[kk * H1 + c], a);
            r[u] = fmaxf(fmaf(a, inv, b1s[c]), 0.0f);
        }
        *(float4*)&xo[c4] = make_float4(r[0], r[1], r[2], r[3]);
    }
}

// ---------------------------------------------------------------------------
// Kernel 3 (fused): gather-sum x1 -> x2 = relu(.@W2*inv+b2) -> out = x2@Wf+bf
// W2 in smem; Wf read via __ldg (L1-resident, identical across blocks) so
// smem drops to ~81KB -> 2 blocks/SM -> 32 warps for latency hiding.
// ---------------------------------------------------------------------------
__device__ __forceinline__ float f4get(float4 v, int kk) {
    return kk == 0 ? v.x : kk == 1 ? v.y : kk == 2 ? v.z : v.w;
}

#define PTS 64

__global__ __launch_bounds__(512, 2)
void layer2_kernel(const float* __restrict__ W2,
                   const float* __restrict__ b2,
                   const float* __restrict__ Wf,
                   const float* __restrict__ bf,
                   float* __restrict__ out) {
    extern __shared__ float smem_f[];
    float* W2s = smem_f;                 // 64*128
    float* b2s = W2s + H1 * H2;          // 128
    float* bfs = b2s + H2;               // 128
    float* s1  = bfs + H2;               // PTS*64
    float* x2s = s1 + PTS * H1;          // PTS*128

    for (int t = threadIdx.x; t < H1 * H2; t += blockDim.x) W2s[t] = W2[t];
    if (threadIdx.x < H2) { b2s[threadIdx.x] = b2[threadIdx.x]; bfs[threadIdx.x] = bf[threadIdx.x]; }

    const int lane = threadIdx.x & 31;
    const int warp = threadIdx.x >> 5;              // 16 warps
    const int gp0  = blockIdx.x * PTS;
    const int b    = gp0 >> 12;
    const float* x1b = g_x1 + (size_t)b * NN * H1;

#pragma unroll
    for (int pp = 0; pp < 4; ++pp) {
        int p  = warp * 4 + pp;
        int gi = gp0 + p;
        int li = gi & (NN - 1);
        const int* nb = g_nbr + (size_t)gi * KNBR;
        float2 v = ((const float2*)(x1b + (size_t)li * H1))[lane];
        float a0 = v.x, a1 = v.y;
#pragma unroll
        for (int n = 0; n < KNBR; ++n) {
            int j = nb[n];
            float2 w = ((const float2*)(x1b + (size_t)j * H1))[lane];
            a0 += w.x; a1 += w.y;
        }
        ((float2*)(s1 + p * H1))[lane] = make_float2(a0, a1);
    }
    __syncthreads();

    const float inv = 1.0f / 17.0f;

    // phase 2: x2 = relu(s1 @ W2 * inv + b2); cols lane*4..lane*4+3
    {
        float acc[4][4];
#pragma unroll
        for (int pp = 0; pp < 4; ++pp)
#pragma unroll
            for (int cc = 0; cc < 4; ++cc) acc[pp][cc] = 0.0f;

#pragma unroll 4
        for (int k = 0; k < H1; k += 4) {
            float4 xv[4];
#pragma unroll
            for (int pp = 0; pp < 4; ++pp)
                xv[pp] = *(const float4*)&s1[(warp * 4 + pp) * H1 + k];
#pragma unroll
            for (int kk = 0; kk < 4; ++kk) {
                float4 w = *(const float4*)&W2s[(k + kk) * H2 + lane * 4];
#pragma unroll
                for (int pp = 0; pp < 4; ++pp) {
                    float xs = f4get(xv[pp], kk);
                    acc[pp][0] = fmaf(xs, w.x, acc[pp][0]);
                    acc[pp][1] = fmaf(xs, w.y, acc[pp][1]);
                    acc[pp][2] = fmaf(xs, w.z, acc[pp][2]);
                    acc[pp][3] = fmaf(xs, w.w, acc[pp][3]);
                }
            }
        }
#pragma unroll
        for (int pp = 0; pp < 4; ++pp) {
            float4 r;
            r.x = fmaxf(fmaf(acc[pp][0], inv, b2s[lane * 4 + 0]), 0.0f);
            r.y = fmaxf(fmaf(acc[pp][1], inv, b2s[lane * 4 + 1]), 0.0f);
            r.z = fmaxf(fmaf(acc[pp][2], inv, b2s[lane * 4 + 2]), 0.0f);
            r.w = fmaxf(fmaf(acc[pp][3], inv, b2s[lane * 4 + 3]), 0.0f);
            *(float4*)&x2s[(warp * 4 + pp) * H2 + lane * 4] = r;
        }
    }
    __syncthreads();

    // phase 3: out = x2 @ Wf + bf  (Wf via __ldg, L1-resident)
    {
        float acc[4][4];
#pragma unroll
        for (int pp = 0; pp < 4; ++pp)
#pragma unroll
            for (int cc = 0; cc < 4; ++cc) acc[pp][cc] = 0.0f;

#pragma unroll 4
        for (int k = 0; k < H2; k += 4) {
            float4 xv[4];
#pragma unroll
            for (int pp = 0; pp < 4; ++pp)
                xv[pp] = *(const float4*)&x2s[(warp * 4 + pp) * H2 + k];
#pragma unroll
            for (int kk = 0; kk < 4; ++kk) {
                float4 w = __ldg((const float4*)&Wf[(k + kk) * H2 + lane * 4]);
#pragma unroll
                for (int pp = 0; pp < 4; ++pp) {
                    float xs = f4get(xv[pp], kk);
                    acc[pp][0] = fmaf(xs, w.x, acc[pp][0]);
                    acc[pp][1] = fmaf(xs, w.y, acc[pp][1]);
                    acc[pp][2] = fmaf(xs, w.z, acc[pp][2]);
                    acc[pp][3] = fmaf(xs, w.w, acc[pp][3]);
                }
            }
        }
#pragma unroll
        for (int pp = 0; pp < 4; ++pp) {
            int gi = gp0 + warp * 4 + pp;
            float4 r;
            r.x = acc[pp][0] + bfs[lane * 4 + 0];
            r.y = acc[pp][1] + bfs[lane * 4 + 1];
            r.z = acc[pp][2] + bfs[lane * 4 + 2];
            r.w = acc[pp][3] + bfs[lane * 4 + 3];
            *(float4*)&out[(size_t)gi * H2 + lane * 4] = r;
        }
    }
}

// ---------------------------------------------------------------------------
extern "C" void kernel_launch(void* const* d_in, const int* in_sizes, int n_in,
                              void* d_out, int out_size) {
    const float* feats = (const float*)d_in[0];
    const float* W1    = (const float*)d_in[1];
    const float* b1    = (const float*)d_in[2];
    const float* W2    = (const float*)d_in[3];
    const float* b2    = (const float*)d_in[4];
    const float* Wf    = (const float*)d_in[5];
    const float* bf    = (const float*)d_in[6];
    float* out = (float*)d_out;

    const int smem_knn = NN * (int)sizeof(float4);                       // 64 KB
    const int smem_l1  = (NN * CC + CC * H1 + H1) * (int)sizeof(float);  // ~98 KB
    const int smem_l2  = (H1 * H2 + 2 * H2 + PTS * H1 + PTS * H2)
                         * (int)sizeof(float);                           // ~81 KB

    cudaFuncSetAttribute(knn_kernel,    cudaFuncAttributeMaxDynamicSharedMemorySize, smem_knn);
    cudaFuncSetAttribute(layer1_kernel, cudaFuncAttributeMaxDynamicSharedMemorySize, smem_l1);
    cudaFuncSetAttribute(layer2_kernel, cudaFuncAttributeMaxDynamicSharedMemorySize, smem_l2);

    dim3 gKNN(NN / 32, BB);                       // 2 queries/warp, 16 warps/block
    knn_kernel   <<<gKNN, 512, smem_knn>>>(feats);
    dim3 gL1(NN / 256, BB);
    layer1_kernel<<<gL1, 256, smem_l1>>>(feats, W1, b1);
    layer2_kernel<<<(BB * NN) / PTS, 512, smem_l2>>>(W2, b2, Wf, bf, out);
}